// round 2
// baseline (speedup 1.0000x reference)
#include <cuda_runtime.h>
#include <cuda_bf16.h>

// Problem constants
#define BB   16
#define SS   4096
#define DIN  1024
#define HH   1024
#define DOUT 1024
#define NS   32              // S-splits for the mean reduction
#define ROWS_PER_SPLIT (SS / NS)   // 128

// Scratch (allocation-free: __device__ globals)
__device__ float g_partial[NS * BB * DIN];  // 2 MiB partial sums
__device__ float g_m[BB * DIN];             // mean(x, axis=1)
__device__ float g_enc[BB * HH];            // encoder activations

// ---------------------------------------------------------------------------
// Kernel 1: partial sums of x over a slice of S.
// Grid: (NS, BB). Block: 256 threads. Thread t owns float4-column t (of 256).
// Streaming loads (__ldcs) — x has zero reuse; keep L2 for the weights.
// ---------------------------------------------------------------------------
__global__ __launch_bounds__(256) void mean_partial_kernel(
    const float* __restrict__ x, float* __restrict__ part)
{
    const int ns = blockIdx.x;
    const int b  = blockIdx.y;
    const int t  = threadIdx.x;                 // 0..255 (float4 column)

    const float4* __restrict__ xp =
        reinterpret_cast<const float4*>(x)
        + (size_t)(b * SS + ns * ROWS_PER_SPLIT) * (DIN / 4) + t;

    float4 acc = make_float4(0.f, 0.f, 0.f, 0.f);
#pragma unroll 8
    for (int s = 0; s < ROWS_PER_SPLIT; ++s) {
        float4 v = __ldcs(xp + (size_t)s * (DIN / 4));
        acc.x += v.x; acc.y += v.y; acc.z += v.z; acc.w += v.w;
    }

    reinterpret_cast<float4*>(part)[(ns * BB + b) * (DIN / 4) + t] = acc;
}

// ---------------------------------------------------------------------------
// Kernel 2: finalize the mean. Grid: (BB). Block: 256.
// ---------------------------------------------------------------------------
__global__ __launch_bounds__(256) void finalize_mean_kernel(
    const float* __restrict__ part, float* __restrict__ m)
{
    const int b = blockIdx.x;
    const int t = threadIdx.x;

    float4 acc = make_float4(0.f, 0.f, 0.f, 0.f);
#pragma unroll
    for (int ns = 0; ns < NS; ++ns) {
        float4 v = reinterpret_cast<const float4*>(part)[(ns * BB + b) * (DIN / 4) + t];
        acc.x += v.x; acc.y += v.y; acc.z += v.z; acc.w += v.w;
    }
    const float inv = 1.0f / (float)SS;
    acc.x *= inv; acc.y *= inv; acc.z *= inv; acc.w *= inv;
    reinterpret_cast<float4*>(m)[b * (DIN / 4) + t] = acc;
}

// ---------------------------------------------------------------------------
// Kernel 3/4: out[b, h] = dot(in[b, :], W[h, :]) + bias[h], for 16 b's.
// Grid: H/8 blocks. Block: 256 threads = 8 warps; one warp per h.
// Each lane keeps 16 batch accumulators; warp-shuffle reduce at the end.
// in is tiny (64 KiB) -> L1/L2 resident; W streamed once (4 MiB).
// ---------------------------------------------------------------------------
__global__ __launch_bounds__(256) void fc16_kernel(
    const float* __restrict__ in,    // [BB, 1024]
    const float* __restrict__ W,     // [Hout, 1024]
    const float* __restrict__ bias,  // [Hout]
    float* __restrict__ out)         // [BB, Hout]
{
    const int warp = threadIdx.x >> 5;
    const int lane = threadIdx.x & 31;
    const int h    = blockIdx.x * 8 + warp;

    const float4* __restrict__ Wp  = reinterpret_cast<const float4*>(W) + (size_t)h * 256;
    const float4* __restrict__ inp = reinterpret_cast<const float4*>(in);

    float acc[BB];
#pragma unroll
    for (int b = 0; b < BB; ++b) acc[b] = 0.f;

#pragma unroll
    for (int k4 = lane; k4 < 256; k4 += 32) {
        float4 wv = __ldg(Wp + k4);
#pragma unroll
        for (int b = 0; b < BB; ++b) {
            float4 mv = __ldg(inp + b * 256 + k4);
            acc[b] += wv.x * mv.x + wv.y * mv.y + wv.z * mv.z + wv.w * mv.w;
        }
    }

    // Warp reduction per batch, lane 0 writes.
    const float bh = __ldg(bias + h);
#pragma unroll
    for (int b = 0; b < BB; ++b) {
        float v = acc[b];
#pragma unroll
        for (int off = 16; off > 0; off >>= 1)
            v += __shfl_xor_sync(0xFFFFFFFFu, v, off);
        if (lane == 0) out[(size_t)b * HH + h] = v + bh;
    }
}

// ---------------------------------------------------------------------------
extern "C" void kernel_launch(void* const* d_in, const int* in_sizes, int n_in,
                              void* d_out, int out_size)
{
    const float* x     = (const float*)d_in[0];   // [16, 4096, 1024]
    const float* W_enc = (const float*)d_in[1];   // [1024, 1024]
    const float* b_enc = (const float*)d_in[2];   // [1024]
    const float* W_out = (const float*)d_in[3];   // [1024, 1024]
    const float* b_out = (const float*)d_in[4];   // [1024]
    float* out = (float*)d_out;                   // [16, 1024]

    float* part; cudaGetSymbolAddress((void**)&part, g_partial);
    float* m;    cudaGetSymbolAddress((void**)&m,    g_m);
    float* enc;  cudaGetSymbolAddress((void**)&enc,  g_enc);

    mean_partial_kernel<<<dim3(NS, BB), 256>>>(x, part);
    finalize_mean_kernel<<<BB, 256>>>(part, m);
    fc16_kernel<<<HH / 8, 256>>>(m, W_enc, b_enc, enc);
    fc16_kernel<<<DOUT / 8, 256>>>(enc, W_out, b_out, out);
}

// round 5
// speedup vs baseline: 1.1282x; 1.1282x over previous
#include <cuda_runtime.h>
#include <cuda_bf16.h>

// Problem constants
#define BB   16
#define SS   4096
#define DIN  1024
#define HH   1024
#define DOUT 1024
#define NS   64                    // S-splits for the mean reduction
#define ROWS_PER_SPLIT (SS / NS)   // 64

// Scratch (allocation-free: __device__ globals)
__device__ float g_partial[NS * BB * DIN];  // 4 MiB partial sums
__device__ float g_m[BB * DIN];             // mean(x, axis=1)
__device__ float g_enc[BB * HH];            // encoder activations

// ---------------------------------------------------------------------------
// Kernel 1: partial sums of x over a slice of S.
// Grid: (NS, BB) = 1024 blocks. Block: 256 threads; thread t owns float4 col t.
// Streaming loads (__ldcs) — x has zero reuse; keep L2 clean.
// ---------------------------------------------------------------------------
__global__ __launch_bounds__(256) void mean_partial_kernel(
    const float* __restrict__ x, float* __restrict__ part)
{
    const int ns = blockIdx.x;
    const int b  = blockIdx.y;
    const int t  = threadIdx.x;                 // 0..255 (float4 column)

    const float4* __restrict__ xp =
        reinterpret_cast<const float4*>(x)
        + (size_t)(b * SS + ns * ROWS_PER_SPLIT) * (DIN / 4) + t;

    float4 acc = make_float4(0.f, 0.f, 0.f, 0.f);
#pragma unroll 16
    for (int s = 0; s < ROWS_PER_SPLIT; ++s) {
        float4 v = __ldcs(xp + (size_t)s * (DIN / 4));
        acc.x += v.x; acc.y += v.y; acc.z += v.z; acc.w += v.w;
    }

    reinterpret_cast<float4*>(part)[(ns * BB + b) * (DIN / 4) + t] = acc;
}

// ---------------------------------------------------------------------------
// Kernel 2: finalize the mean. Grid: (BB). Block: 256.
// ---------------------------------------------------------------------------
__global__ __launch_bounds__(256) void finalize_mean_kernel(
    const float* __restrict__ part, float* __restrict__ m)
{
    const int b = blockIdx.x;
    const int t = threadIdx.x;

    float4 acc = make_float4(0.f, 0.f, 0.f, 0.f);
#pragma unroll
    for (int ns = 0; ns < NS; ++ns) {
        float4 v = reinterpret_cast<const float4*>(part)[(ns * BB + b) * (DIN / 4) + t];
        acc.x += v.x; acc.y += v.y; acc.z += v.z; acc.w += v.w;
    }
    const float inv = 1.0f / (float)SS;
    acc.x *= inv; acc.y *= inv; acc.z *= inv; acc.w *= inv;
    reinterpret_cast<float4*>(m)[b * (DIN / 4) + t] = acc;
}

// ---------------------------------------------------------------------------
// Kernel 3/4: out[b, h] = dot(in[b, :], W[h, :]) + bias[h], for all 16 b's.
// One block per h (grid=1024). 256 threads; thread t owns float4 column t of
// W[h] -> a single fully independent W load per thread (max MLP chip-wide).
// in (64 KB) is L1-resident. Shuffle + smem block reduction.
// ---------------------------------------------------------------------------
__global__ __launch_bounds__(256) void fc16_kernel(
    const float* __restrict__ in,    // [BB, 1024]
    const float* __restrict__ W,     // [Hout, 1024]
    const float* __restrict__ bias,  // [Hout]
    float* __restrict__ out)         // [BB, Hout]
{
    const int h    = blockIdx.x;
    const int t    = threadIdx.x;
    const int lane = t & 31;
    const int w    = t >> 5;

    const float4 wv = __ldg(reinterpret_cast<const float4*>(W) + (size_t)h * 256 + t);
    const float4* __restrict__ inp = reinterpret_cast<const float4*>(in);

    float acc[BB];
#pragma unroll
    for (int b = 0; b < BB; ++b) {
        float4 mv = __ldg(inp + b * 256 + t);
        acc[b] = wv.x * mv.x + wv.y * mv.y + wv.z * mv.z + wv.w * mv.w;
    }

    __shared__ float red[BB * 8];
#pragma unroll
    for (int b = 0; b < BB; ++b) {
        float v = acc[b];
#pragma unroll
        for (int off = 16; off > 0; off >>= 1)
            v += __shfl_xor_sync(0xFFFFFFFFu, v, off);
        if (lane == 0) red[b * 8 + w] = v;
    }
    __syncthreads();

    if (t < BB) {
        float s = 0.f;
#pragma unroll
        for (int w2 = 0; w2 < 8; ++w2) s += red[t * 8 + w2];
        out[(size_t)t * HH + h] = s + __ldg(bias + h);
    }
}

// ---------------------------------------------------------------------------
extern "C" void kernel_launch(void* const* d_in, const int* in_sizes, int n_in,
                              void* d_out, int out_size)
{
    const float* x     = (const float*)d_in[0];   // [16, 4096, 1024]
    const float* W_enc = (const float*)d_in[1];   // [1024, 1024]
    const float* b_enc = (const float*)d_in[2];   // [1024]
    const float* W_out = (const float*)d_in[3];   // [1024, 1024]
    const float* b_out = (const float*)d_in[4];   // [1024]
    float* out = (float*)d_out;                   // [16, 1024]

    float* part; cudaGetSymbolAddress((void**)&part, g_partial);
    float* m;    cudaGetSymbolAddress((void**)&m,    g_m);
    float* enc;  cudaGetSymbolAddress((void**)&enc,  g_enc);

    mean_partial_kernel<<<dim3(NS, BB), 256>>>(x, part);
    finalize_mean_kernel<<<BB, 256>>>(part, m);
    fc16_kernel<<<HH, 256>>>(m, W_enc, b_enc, enc);
    fc16_kernel<<<DOUT, 256>>>(enc, W_out, b_out, out);
}